// round 1
// baseline (speedup 1.0000x reference)
#include <cuda_runtime.h>
#include <math_constants.h>

#define N_SRC 100000
#define MROWS 20000
#define KNEI 32
#define HDIM 128
#define NEG_SLOPE 0.01f
#define FULLM 0xffffffffu

// Scratch (allocation-free rule: __device__ globals)
__device__ float2 g_xf[N_SRC];   // (x, f(x)) per source node
__device__ float2 g_wl[HDIM];    // (wl, bl) permuted by descending ratio r = bl/wl
__device__ float  g_r[HDIM];     // sorted ratios, descending
__device__ float2 g_wr[HDIM];    // (wr, br) same permutation
__device__ float  g_aref[HDIM];  // a_ref same permutation

// ---------------------------------------------------------------------------
// Kernel 0: one block, 128 threads. Rank-sort j by r = bl/wl descending,
// write permuted parameter copies.
// ---------------------------------------------------------------------------
__global__ void prep_kernel(const float* __restrict__ wl, const float* __restrict__ bl,
                            const float* __restrict__ wr, const float* __restrict__ br,
                            const float* __restrict__ att_inter) {
    int j = threadIdx.x;
    __shared__ float sr[HDIM];
    float w = wl[j], b = bl[j];
    float r;
    if (w > 0.f) r = b / w;
    else         r = (b > 0.f) ? CUDART_INF_F : -CUDART_INF_F;  // never NaN
    sr[j] = r;
    __syncthreads();
    int rank = 0;
    #pragma unroll 8
    for (int k = 0; k < HDIM; k++) {
        float rk = sr[k];
        rank += (rk > r) || (rk == r && k < j);   // stable descending
    }
    g_wl[rank]   = make_float2(w, b);
    g_r[rank]    = r;
    g_wr[rank]   = make_float2(wr[j], br[j]);
    g_aref[rank] = att_inter[j];                  // a_ref = att_inter[0:H]
}

// ---------------------------------------------------------------------------
// Kernel 1: per-source-node table (x, f(x)), f(x)=sum_j relu(x*wl+bl)*a_nei
// Uses ORIGINAL (unpermuted) params — sums are order-independent.
// ---------------------------------------------------------------------------
__global__ void __launch_bounds__(256) node_kernel(const float* __restrict__ h,
                            const float* __restrict__ wl, const float* __restrict__ bl,
                            const float* __restrict__ anei) {
    __shared__ float2 swl[HDIM];
    __shared__ float  sa[HDIM];
    if (threadIdx.x < HDIM) {
        swl[threadIdx.x] = make_float2(wl[threadIdx.x], bl[threadIdx.x]);
        sa[threadIdx.x]  = anei[threadIdx.x];
    }
    __syncthreads();
    int i = blockIdx.x * blockDim.x + threadIdx.x;
    if (i >= N_SRC) return;
    float x = h[i];
    float f = 0.f;
    #pragma unroll 16
    for (int j = 0; j < HDIM; j++) {
        float e = fmaxf(fmaf(x, swl[j].x, swl[j].y), 0.f);
        f = fmaf(e, sa[j], f);
    }
    g_xf[i] = make_float2(x, f);
}

// ---------------------------------------------------------------------------
// Kernel 2: main. One warp per row m; 8 warps / block.
// ---------------------------------------------------------------------------
__global__ void __launch_bounds__(256) main_kernel(const int* __restrict__ nei,
                            const float* __restrict__ h_refer,
                            float* __restrict__ out, float* __restrict__ attOut) {
    __shared__ float2 s_wl[HDIM];
    __shared__ float  s_r[HDIM];
    __shared__ float2 s_wr[HDIM];
    __shared__ float  s_aref[HDIM];
    __shared__ float2 s_pref[8][HDIM + 1];   // per-warp prefix sums of (wl*hr, bl*hr)

    int tid = threadIdx.x;
    if (tid < HDIM) {
        s_wl[tid]   = g_wl[tid];
        s_r[tid]    = g_r[tid];
        s_wr[tid]   = g_wr[tid];
        s_aref[tid] = g_aref[tid];
    }
    __syncthreads();

    int warp = tid >> 5, lane = tid & 31;
    int m = blockIdx.x * 8 + warp;

    float y = h_refer[m];
    float a[4], b[4];
    float gp = 0.f;
    #pragma unroll
    for (int i = 0; i < 4; i++) {           // lane owns contiguous j = 4*lane+i
        int j = lane * 4 + i;
        float2 wr2 = s_wr[j];
        float hr = fmaxf(fmaf(y, wr2.x, wr2.y), 0.f);
        gp = fmaf(hr, s_aref[j], gp);       // g_m = hr . a_ref
        float2 wl2 = s_wl[j];
        a[i] = wl2.x * hr;                  // wl_j * hr_j
        b[i] = wl2.y * hr;                  // bl_j * hr_j
    }
    // local inclusive scans
    a[1] += a[0]; a[2] += a[1]; a[3] += a[2];
    b[1] += b[0]; b[2] += b[1]; b[3] += b[2];
    // warp scan of lane totals
    float ta = a[3], tb = b[3];
    #pragma unroll
    for (int o = 1; o < 32; o <<= 1) {
        float va = __shfl_up_sync(FULLM, ta, o);
        float vb = __shfl_up_sync(FULLM, tb, o);
        if (lane >= o) { ta += va; tb += vb; }
    }
    float offA = ta - a[3], offB = tb - b[3];   // exclusive lane offset
    if (lane == 0) s_pref[warp][0] = make_float2(0.f, 0.f);
    #pragma unroll
    for (int i = 0; i < 4; i++)
        s_pref[warp][lane * 4 + i + 1] = make_float2(offA + a[i], offB + b[i]);

    #pragma unroll
    for (int o = 16; o; o >>= 1) gp += __shfl_xor_sync(FULLM, gp, o);  // g in all lanes
    __syncwarp();   // order pref stores before per-lane random reads

    // ---- lane = neighbor k ----
    int idx = nei[m * KNEI + lane];
    float2 xf = g_xf[idx];
    float x = xf.x;
    float logit = gp + xf.y;
    logit = (logit >= 0.f) ? logit : NEG_SLOPE * logit;

    float lr;
    if (x >= 0.f) {                        // all H terms active (wl,bl >= 0)
        float2 p = s_pref[warp][HDIM];
        lr = fmaf(x, p.x, p.y);
    } else {                               // active set = prefix of sorted-r order
        float t = -x;
        int lo = 0, hi = HDIM;
        while (lo < hi) {                  // count of r_j > t (descending array)
            int mid = (lo + hi) >> 1;
            if (s_r[mid] > t) lo = mid + 1; else hi = mid;
        }
        float2 p = s_pref[warp][lo];
        lr = fmaf(x, p.x, p.y);
    }

    // softmax over 32 lanes (max-subtracted, like jax.nn.softmax)
    float mx = logit;
    #pragma unroll
    for (int o = 16; o; o >>= 1) mx = fmaxf(mx, __shfl_xor_sync(FULLM, mx, o));
    float e = __expf(logit - mx);
    float s = e;
    #pragma unroll
    for (int o = 16; o; o >>= 1) s += __shfl_xor_sync(FULLM, s, o);
    float att = e / s;

    float acc = att * lr;
    #pragma unroll
    for (int o = 16; o; o >>= 1) acc += __shfl_xor_sync(FULLM, acc, o);

    if (lane == 0) out[m] = fmaxf(acc, 0.f);
    attOut[m * KNEI + lane] = att;
}

// ---------------------------------------------------------------------------
extern "C" void kernel_launch(void* const* d_in, const int* in_sizes, int n_in,
                              void* d_out, int out_size) {
    const int*   nei       = (const int*)  d_in[0];
    const float* h         = (const float*)d_in[1];
    const float* h_refer   = (const float*)d_in[2];
    const float* map_l_w   = (const float*)d_in[3];
    const float* map_l_b   = (const float*)d_in[4];
    const float* map_r_w   = (const float*)d_in[5];
    const float* map_r_b   = (const float*)d_in[6];
    const float* att_inter = (const float*)d_in[7];

    float* out    = (float*)d_out;          // [M]
    float* attOut = out + MROWS;            // [M, K] flattened after out

    prep_kernel<<<1, HDIM>>>(map_l_w, map_l_b, map_r_w, map_r_b, att_inter);
    node_kernel<<<(N_SRC + 255) / 256, 256>>>(h, map_l_w, map_l_b, att_inter + HDIM);
    main_kernel<<<MROWS / 8, 256>>>(nei, h_refer, out, attOut);
}